// round 3
// baseline (speedup 1.0000x reference)
#include <cuda_runtime.h>

#define NB 8
#define NBATCH 64
#define SEQ 1024
#define DIM 64
#define UDIM 128
#define SIGDIM 4160   // 64 + 64*64

// ---------------- device scratch (no allocations allowed) ----------------
__device__ float g_sig[NBATCH * SIGDIM];
__device__ float g_hacc[NBATCH * UDIM];
__device__ float g_skip[NBATCH * UDIM];
__device__ float g_wts[NBATCH * UDIM];

// ---------------- helpers ----------------
__device__ __forceinline__ float siluf(float x) { return x / (1.f + __expf(-x)); }
__device__ __forceinline__ float sigm(float x) { return 1.f / (1.f + __expf(-x)); }

// Cox-de Boor, order 3, uniform knots grid[i] = (i-3)*0.4 - 1, i=0..11 -> 8 bases
__device__ __forceinline__ void bspl8(float x, float* o) {
    float b[11];
#pragma unroll
    for (int i = 0; i < 11; i++) {
        float g0 = (i - 3) * 0.4f - 1.0f;
        float g1 = (i - 2) * 0.4f - 1.0f;
        b[i] = (x >= g0 && x < g1) ? 1.f : 0.f;
    }
#pragma unroll
    for (int p = 1; p <= 3; p++) {
        float inv = 1.f / (0.4f * (float)p);
#pragma unroll
        for (int i = 0; i + p < 11; i++) {
            float gi  = (i - 3) * 0.4f - 1.0f;       // grid[i]
            float gip = (i + p - 2) * 0.4f - 1.0f;   // grid[i+p+1]
            b[i] = (x - gi) * inv * b[i] + (gip - x) * inv * b[i + 1];
        }
    }
#pragma unroll
    for (int i = 0; i < 8; i++) o[i] = b[i];
}

// ---------------- K1: path signature (one block per batch) ----------------
// S2[i][j] = sum_t (P_t[i] + 0.5*u_t[i]) * u_t[j],  P = exclusive prefix of u
__global__ __launch_bounds__(256) void k_sig(const float* __restrict__ x,
                                             const float* __restrict__ tw) {
    __shared__ float Ush[64 * 68];
    __shared__ float Qsh[64 * 68];
    __shared__ float segsum[4][64];
    __shared__ float carry[64];

    const int b = blockIdx.x, tid = threadIdx.x;

    // zero the GRKAN accumulators (64 blocks * 256 threads == 16384 == 2*8192)
    {
        int g = b * 256 + tid;
        if (g < NBATCH * UDIM) g_hacc[g] = 0.f;
        else g_skip[g - NBATCH * UDIM] = 0.f;
    }

    const int d = tid & 63, seg = tid >> 6;
    if (tid < 64) carry[tid] = 0.f;

    float acc[4][4];
#pragma unroll
    for (int a = 0; a < 4; a++)
#pragma unroll
        for (int c = 0; c < 4; c++) acc[a][c] = 0.f;

    const int i0 = (tid & 15) * 4;   // prefix index (S2 row)
    const int j0 = (tid >> 4) * 4;   // increment index (S2 col)
    const float* xb = x + (size_t)b * SEQ * DIM;

    for (int t0 = 0; t0 < SEQ - 1; t0 += 64) {
        const int T = min(64, (SEQ - 1) - t0);
        __syncthreads();  // protect Ush/Qsh reuse + carry init on first iter

        for (int idx = tid; idx < T * 64; idx += 256) {
            int t = idx >> 6, dd = idx & 63;
            int gt = t0 + t;
            Ush[t * 68 + dd] = tw[gt + 1] * xb[(gt + 1) * DIM + dd]
                             - tw[gt]     * xb[gt * DIM + dd];
        }
        __syncthreads();

        // hierarchical exclusive prefix over t, per dim d (4 segments of 16)
        const int ss = seg * 16;
        const int se = min(ss + 16, T);
        float ssum = 0.f;
        for (int t = ss; t < se; t++) ssum += Ush[t * 68 + d];
        segsum[seg][d] = ssum;
        __syncthreads();
        float off = carry[d];
        for (int s = 0; s < seg; s++) off += segsum[s][d];
        __syncthreads();  // all carry reads done before seg3 updates it
        float p = off;
        for (int t = ss; t < se; t++) {
            float u = Ush[t * 68 + d];
            Qsh[t * 68 + d] = p + 0.5f * u;
            p += u;
        }
        if (seg == 3) carry[d] = p;
        __syncthreads();

        // rank-1-accumulate: acc[i][j] += Q[k][i]*U[k][j]
        for (int k = 0; k < T; k++) {
            float4 q  = *(const float4*)&Qsh[k * 68 + i0];
            float4 u4 = *(const float4*)&Ush[k * 68 + j0];
            acc[0][0] += q.x * u4.x; acc[0][1] += q.x * u4.y; acc[0][2] += q.x * u4.z; acc[0][3] += q.x * u4.w;
            acc[1][0] += q.y * u4.x; acc[1][1] += q.y * u4.y; acc[1][2] += q.y * u4.z; acc[1][3] += q.y * u4.w;
            acc[2][0] += q.z * u4.x; acc[2][1] += q.z * u4.y; acc[2][2] += q.z * u4.z; acc[2][3] += q.z * u4.w;
            acc[3][0] += q.w * u4.x; acc[3][1] += q.w * u4.y; acc[3][2] += q.w * u4.z; acc[3][3] += q.w * u4.w;
        }
    }
    __syncthreads();

    float* sb = g_sig + (size_t)b * SIGDIM;
#pragma unroll
    for (int a = 0; a < 4; a++) {
        float4 v = make_float4(acc[a][0], acc[a][1], acc[a][2], acc[a][3]);
        *(float4*)&sb[64 + (i0 + a) * 64 + j0] = v;
    }
    if (tid < 64)
        sb[tid] = tw[SEQ - 1] * xb[(SEQ - 1) * DIM + tid] - tw[0] * xb[tid];
}

// ---------------- K2: GRKAN layer 1 + skip, split-K over sig inputs ----------------
// h1[b][u] += silu(sig)*g1_base + bases*g1_spline ; skip[b][u] += sig*skip_w
__global__ __launch_bounds__(256) void k_grkan1(const float* __restrict__ g1b,
                                                const float* __restrict__ g1s,
                                                const float* __restrict__ skw) {
    __shared__ float st[64 * 33];        // sig tile [batch][32 inputs]
    __shared__ float fb[2 * 64 * 9];     // features [dp][batch][9]
    __shared__ float wb[2 * 10 * 128];   // weight rows [dp][k(0..9)][u]

    const int tid = threadIdx.x;
    const int in0 = blockIdx.x * 32;

    for (int idx = tid; idx < 64 * 32; idx += 256) {
        int bb = idx >> 5, i = idx & 31;
        st[bb * 33 + i] = g_sig[(size_t)bb * SIGDIM + in0 + i];
    }

    float ah[4][8], as[4][8];
#pragma unroll
    for (int i = 0; i < 4; i++)
#pragma unroll
        for (int j = 0; j < 8; j++) { ah[i][j] = 0.f; as[i][j] = 0.f; }

    const int cg = tid & 15, rg = tid >> 4;
    const int c0 = cg * 8, r0 = rg * 4;

    for (int dl = 0; dl < 32; dl += 2) {
        __syncthreads();  // tile ready (first iter) / buffers free (later iters)
        if (tid < 128) {
            int bb = tid & 63, dp = tid >> 6;
            float xv = st[bb * 33 + dl + dp];
            float* f = &fb[(dp * 64 + bb) * 9];
            f[0] = siluf(xv);
            bspl8(xv, f + 1);
        }
        for (int idx = tid; idx < 2560; idx += 256) {
            int c = idx & 127, row = idx >> 7;  // row = dp*10 + k
            int dp = row / 10, k = row - dp * 10;
            int in = in0 + dl + dp;
            float w;
            if (k == 0) w = g1b[in * UDIM + c];
            else if (k < 9) w = g1s[(in * NB + (k - 1)) * UDIM + c];
            else w = skw[in * UDIM + c];
            wb[row * 128 + c] = w;
        }
        __syncthreads();

#pragma unroll
        for (int dp = 0; dp < 2; dp++) {
#pragma unroll
            for (int k = 0; k < 9; k++) {
                float4 w0 = *(const float4*)&wb[(dp * 10 + k) * 128 + c0];
                float4 w1 = *(const float4*)&wb[(dp * 10 + k) * 128 + c0 + 4];
#pragma unroll
                for (int i = 0; i < 4; i++) {
                    float f = fb[(dp * 64 + r0 + i) * 9 + k];
                    ah[i][0] += f * w0.x; ah[i][1] += f * w0.y; ah[i][2] += f * w0.z; ah[i][3] += f * w0.w;
                    ah[i][4] += f * w1.x; ah[i][5] += f * w1.y; ah[i][6] += f * w1.z; ah[i][7] += f * w1.w;
                }
            }
            {   // raw value for skip path
                float4 w0 = *(const float4*)&wb[(dp * 10 + 9) * 128 + c0];
                float4 w1 = *(const float4*)&wb[(dp * 10 + 9) * 128 + c0 + 4];
#pragma unroll
                for (int i = 0; i < 4; i++) {
                    float rv = st[(r0 + i) * 33 + dl + dp];
                    as[i][0] += rv * w0.x; as[i][1] += rv * w0.y; as[i][2] += rv * w0.z; as[i][3] += rv * w0.w;
                    as[i][4] += rv * w1.x; as[i][5] += rv * w1.y; as[i][6] += rv * w1.z; as[i][7] += rv * w1.w;
                }
            }
        }
    }

#pragma unroll
    for (int i = 0; i < 4; i++)
#pragma unroll
        for (int j = 0; j < 8; j++) {
            atomicAdd(&g_hacc[(r0 + i) * UDIM + c0 + j], ah[i][j]);
            atomicAdd(&g_skip[(r0 + i) * UDIM + c0 + j], as[i][j]);
        }
}

// ---------------- K3: GRKAN layer 2, gate, layernorm, softmax ----------------
__global__ __launch_bounds__(128) void k_grkan2(const float* __restrict__ g2b,
                                                const float* __restrict__ g2s,
                                                const float* __restrict__ gws,
                                                const float* __restrict__ gbs,
                                                const float* __restrict__ gwv,
                                                const float* __restrict__ gbv,
                                                const float* __restrict__ skb,
                                                const float* __restrict__ lng,
                                                const float* __restrict__ lnb) {
    __shared__ float f2[128 * 9];
    __shared__ float h2s[128];
    __shared__ float red[4];

    const int b = blockIdx.x, u = threadIdx.x;

    auto blocksum = [&](float v) -> float {
#pragma unroll
        for (int o = 16; o; o >>= 1) v += __shfl_xor_sync(0xffffffffu, v, o);
        __syncthreads();
        if ((threadIdx.x & 31) == 0) red[threadIdx.x >> 5] = v;
        __syncthreads();
        return red[0] + red[1] + red[2] + red[3];
    };
    auto blockmax = [&](float v) -> float {
#pragma unroll
        for (int o = 16; o; o >>= 1) v = fmaxf(v, __shfl_xor_sync(0xffffffffu, v, o));
        __syncthreads();
        if ((threadIdx.x & 31) == 0) red[threadIdx.x >> 5] = v;
        __syncthreads();
        return fmaxf(fmaxf(red[0], red[1]), fmaxf(red[2], red[3]));
    };

    float hv = g_hacc[b * UDIM + u];
    float sk = g_skip[b * UDIM + u] + skb[u];

    f2[u * 9] = siluf(hv);
    bspl8(hv, &f2[u * 9 + 1]);
    __syncthreads();

    float a0 = 0.f, a1 = 0.f, a2 = 0.f;
    for (int v = 0; v < 128; v++) {
        const float* fr = &f2[v * 9];
        a0 += fr[0] * g2b[v * UDIM + u];
#pragma unroll
        for (int k = 0; k < 4; k++) a1 += fr[1 + k] * g2s[(v * NB + k) * UDIM + u];
#pragma unroll
        for (int k = 4; k < 8; k++) a2 += fr[1 + k] * g2s[(v * NB + k) * UDIM + u];
    }
    float h2 = a0 + a1 + a2;
    h2s[u] = h2;
    __syncthreads();

    float gs = gbs[u], gv = gbv[u];
    for (int v = 0; v < 128; v++) {
        float hh = h2s[v];
        gs += hh * gws[v * UDIM + u];
        gv += hh * gwv[v * UDIM + u];
    }
    float pre = sk + sigm(gs) * gv;

    float s1 = blocksum(pre);
    float s2 = blocksum(pre * pre);
    float mu = s1 * (1.f / 128.f);
    float var = s2 * (1.f / 128.f) - mu * mu;
    float y = lng[u] * (pre - mu) * rsqrtf(var + 1e-3f) + lnb[u];

    float m = blockmax(y);
    float e = __expf(y - m);
    float se = blocksum(e);
    g_wts[b * UDIM + u] = e / se;
}

// ---------------- K4: main KAN over all (b,s) rows, fused weight multiply ----------------
__global__ __launch_bounds__(256) void k_main(const float* __restrict__ x,
                                              const float* __restrict__ tw,
                                              const float* __restrict__ kb,
                                              const float* __restrict__ ksp,
                                              float* __restrict__ out) {
    __shared__ float xt[128 * 65];   // w = tw*x tile, 128 rows x 64 dims
    __shared__ float fb[128 * 9];    // features for current dim d
    __shared__ float wb[9 * 128];    // weight rows for current dim d

    const int tid = threadIdx.x;
    const int row0 = blockIdx.x * 128;
    const int b = row0 >> 10;
    const int s0 = row0 & (SEQ - 1);

    for (int idx = tid; idx < 128 * 64; idx += 256) {
        int r = idx >> 6, d = idx & 63;
        xt[r * 65 + d] = tw[s0 + r] * x[(size_t)(row0 + r) * DIM + d];
    }

    float acc[8][8];
#pragma unroll
    for (int i = 0; i < 8; i++)
#pragma unroll
        for (int j = 0; j < 8; j++) acc[i][j] = 0.f;

    const int cg = tid & 15, rg = tid >> 4;
    const int c0 = cg * 8, r0 = rg * 8;

    for (int d = 0; d < 64; d++) {
        __syncthreads();  // xt ready (first) / fb,wb free (later)
        if (tid < 128) {
            float xv = xt[tid * 65 + d];
            float* f = &fb[tid * 9];
            f[0] = siluf(xv);
            bspl8(xv, f + 1);
        }
        for (int idx = tid; idx < 1152; idx += 256) {
            int k = idx >> 7, c = idx & 127;
            wb[idx] = (k == 0) ? kb[d * UDIM + c] : ksp[(d * NB + k - 1) * UDIM + c];
        }
        __syncthreads();

#pragma unroll
        for (int k = 0; k < 9; k++) {
            float4 w0 = *(const float4*)&wb[k * 128 + c0];
            float4 w1 = *(const float4*)&wb[k * 128 + c0 + 4];
#pragma unroll
            for (int i = 0; i < 8; i++) {
                float f = fb[(r0 + i) * 9 + k];
                acc[i][0] += f * w0.x; acc[i][1] += f * w0.y; acc[i][2] += f * w0.z; acc[i][3] += f * w0.w;
                acc[i][4] += f * w1.x; acc[i][5] += f * w1.y; acc[i][6] += f * w1.z; acc[i][7] += f * w1.w;
            }
        }
    }

    float wv[8];
#pragma unroll
    for (int j = 0; j < 8; j++) wv[j] = g_wts[b * UDIM + c0 + j];
#pragma unroll
    for (int i = 0; i < 8; i++) {
        int row = row0 + r0 + i;
        float4 o0 = make_float4(acc[i][0] * wv[0], acc[i][1] * wv[1],
                                acc[i][2] * wv[2], acc[i][3] * wv[3]);
        float4 o1 = make_float4(acc[i][4] * wv[4], acc[i][5] * wv[5],
                                acc[i][6] * wv[6], acc[i][7] * wv[7]);
        *(float4*)&out[(size_t)row * UDIM + c0] = o0;
        *(float4*)&out[(size_t)row * UDIM + c0 + 4] = o1;
    }
}

// ---------------- launch ----------------
extern "C" void kernel_launch(void* const* d_in, const int* in_sizes, int n_in,
                              void* d_out, int out_size) {
    const float* x   = (const float*)d_in[0];
    const float* tw  = (const float*)d_in[1];
    const float* kb  = (const float*)d_in[2];
    const float* ksp = (const float*)d_in[3];
    const float* g1b = (const float*)d_in[4];
    const float* g1s = (const float*)d_in[5];
    const float* g2b = (const float*)d_in[6];
    const float* g2s = (const float*)d_in[7];
    const float* skw = (const float*)d_in[8];
    const float* skb = (const float*)d_in[9];
    const float* gws = (const float*)d_in[10];
    const float* gbs = (const float*)d_in[11];
    const float* gwv = (const float*)d_in[12];
    const float* gbv = (const float*)d_in[13];
    const float* lng = (const float*)d_in[14];
    const float* lnb = (const float*)d_in[15];
    float* out = (float*)d_out;

    k_sig<<<NBATCH, 256>>>(x, tw);                 // signature + zero accumulators
    k_grkan1<<<130, 256>>>(g1b, g1s, skw);         // split-K layer-1 + skip
    k_grkan2<<<NBATCH, 128>>>(g2b, g2s, gws, gbs, gwv, gbv, skb, lng, lnb);
    k_main<<<512, 256>>>(x, tw, kb, ksp, out);     // dominant KAN GEMM + weight mul
}

// round 4
// speedup vs baseline: 1.8150x; 1.8150x over previous
#include <cuda_runtime.h>

#define NB 8
#define NBATCH 64
#define SEQ 1024
#define DIM 64
#define UDIM 128
#define SIGDIM 4160   // 64 + 64*64

// ---------------- device scratch (no allocations allowed) ----------------
__device__ float g_sig[NBATCH * SIGDIM];
__device__ float g_hacc[NBATCH * UDIM];
__device__ float g_skip[NBATCH * UDIM];
__device__ float g_wts[NBATCH * UDIM];

// ---------------- helpers ----------------
__device__ __forceinline__ float siluf(float x) { return x / (1.f + __expf(-x)); }
__device__ __forceinline__ float sigm(float x) { return 1.f / (1.f + __expf(-x)); }

// packed dual-lane fp32 FMA (sm_100+, only reachable via PTX)
__device__ __forceinline__ void ffma2(unsigned long long& acc,
                                      unsigned long long f,
                                      unsigned long long w) {
    asm("fma.rn.f32x2 %0, %1, %2, %0;" : "+l"(acc) : "l"(f), "l"(w));
}

// Cox-de Boor, order 3, uniform knots grid[i] = (i-3)*0.4 - 1, i=0..11 -> 8 bases
__device__ __forceinline__ void bspl8(float x, float* o) {
    float b[11];
#pragma unroll
    for (int i = 0; i < 11; i++) {
        float g0 = (i - 3) * 0.4f - 1.0f;
        float g1 = (i - 2) * 0.4f - 1.0f;
        b[i] = (x >= g0 && x < g1) ? 1.f : 0.f;
    }
#pragma unroll
    for (int p = 1; p <= 3; p++) {
        float inv = 1.f / (0.4f * (float)p);
#pragma unroll
        for (int i = 0; i + p < 11; i++) {
            float gi  = (i - 3) * 0.4f - 1.0f;       // grid[i]
            float gip = (i + p - 2) * 0.4f - 1.0f;   // grid[i+p+1]
            b[i] = (x - gi) * inv * b[i] + (gip - x) * inv * b[i + 1];
        }
    }
#pragma unroll
    for (int i = 0; i < 8; i++) o[i] = b[i];
}

// ---------------- K1: path signature (one block per batch) ----------------
// S2[i][j] = sum_t (P_t[i] + 0.5*u_t[i]) * u_t[j],  P = exclusive prefix of u
__global__ __launch_bounds__(256) void k_sig(const float* __restrict__ x,
                                             const float* __restrict__ tw) {
    __shared__ __align__(16) float Ush[64 * 68];
    __shared__ __align__(16) float Qsh[64 * 68];
    __shared__ float segsum[4][64];
    __shared__ float carry[64];

    const int b = blockIdx.x, tid = threadIdx.x;

    // zero the GRKAN accumulators (64 blocks * 256 threads == 16384 == 2*8192)
    {
        int g = b * 256 + tid;
        if (g < NBATCH * UDIM) g_hacc[g] = 0.f;
        else g_skip[g - NBATCH * UDIM] = 0.f;
    }

    const int d = tid & 63, seg = tid >> 6;
    if (tid < 64) carry[tid] = 0.f;

    float acc[4][4];
#pragma unroll
    for (int a = 0; a < 4; a++)
#pragma unroll
        for (int c = 0; c < 4; c++) acc[a][c] = 0.f;

    const int i0 = (tid & 15) * 4;   // prefix index (S2 row)
    const int j0 = (tid >> 4) * 4;   // increment index (S2 col)
    const float* xb = x + (size_t)b * SEQ * DIM;

    for (int t0 = 0; t0 < SEQ - 1; t0 += 64) {
        const int T = min(64, (SEQ - 1) - t0);
        __syncthreads();

        for (int idx = tid; idx < T * 64; idx += 256) {
            int t = idx >> 6, dd = idx & 63;
            int gt = t0 + t;
            Ush[t * 68 + dd] = tw[gt + 1] * xb[(gt + 1) * DIM + dd]
                             - tw[gt]     * xb[gt * DIM + dd];
        }
        __syncthreads();

        const int ss = seg * 16;
        const int se = min(ss + 16, T);
        float ssum = 0.f;
        for (int t = ss; t < se; t++) ssum += Ush[t * 68 + d];
        segsum[seg][d] = ssum;
        __syncthreads();
        float off = carry[d];
        for (int s = 0; s < seg; s++) off += segsum[s][d];
        __syncthreads();
        float p = off;
        for (int t = ss; t < se; t++) {
            float u = Ush[t * 68 + d];
            Qsh[t * 68 + d] = p + 0.5f * u;
            p += u;
        }
        if (seg == 3) carry[d] = p;
        __syncthreads();

        for (int k = 0; k < T; k++) {
            float4 q  = *(const float4*)&Qsh[k * 68 + i0];
            float4 u4 = *(const float4*)&Ush[k * 68 + j0];
            acc[0][0] += q.x * u4.x; acc[0][1] += q.x * u4.y; acc[0][2] += q.x * u4.z; acc[0][3] += q.x * u4.w;
            acc[1][0] += q.y * u4.x; acc[1][1] += q.y * u4.y; acc[1][2] += q.y * u4.z; acc[1][3] += q.y * u4.w;
            acc[2][0] += q.z * u4.x; acc[2][1] += q.z * u4.y; acc[2][2] += q.z * u4.z; acc[2][3] += q.z * u4.w;
            acc[3][0] += q.w * u4.x; acc[3][1] += q.w * u4.y; acc[3][2] += q.w * u4.z; acc[3][3] += q.w * u4.w;
        }
    }
    __syncthreads();

    float* sb = g_sig + (size_t)b * SIGDIM;
#pragma unroll
    for (int a = 0; a < 4; a++) {
        float4 v = make_float4(acc[a][0], acc[a][1], acc[a][2], acc[a][3]);
        *(float4*)&sb[64 + (i0 + a) * 64 + j0] = v;
    }
    if (tid < 64)
        sb[tid] = tw[SEQ - 1] * xb[(SEQ - 1) * DIM + tid] - tw[0] * xb[tid];
}

// ---------------- K2: GRKAN layer 1 + skip (FFMA2), split-K over sig inputs ----------------
__global__ __launch_bounds__(256, 2) void k_grkan1(const float* __restrict__ g1b,
                                                   const float* __restrict__ g1s,
                                                   const float* __restrict__ skw) {
    __shared__ __align__(16) float st[64 * 33];      // sig tile [batch][32 inputs]
    __shared__ __align__(16) float2 fb2[2 * 64 * 10];// duplicated feats [dp][batch][10]
    __shared__ __align__(16) float wb[2 * 10 * 128]; // weight rows [dp][k(0..9)][u]

    const int tid = threadIdx.x;
    const int in0 = blockIdx.x * 32;

    for (int idx = tid; idx < 64 * 32; idx += 256) {
        int bb = idx >> 5, i = idx & 31;
        st[bb * 33 + i] = g_sig[(size_t)bb * SIGDIM + in0 + i];
    }

    unsigned long long ah2[4][4], as2[4][4];
    const unsigned long long Z = 0ull;
#pragma unroll
    for (int i = 0; i < 4; i++)
#pragma unroll
        for (int j = 0; j < 4; j++) { ah2[i][j] = Z; as2[i][j] = Z; }

    const int cg = tid & 15, rg = tid >> 4;
    const int c0 = cg * 8, r0 = rg * 4;

    for (int dl = 0; dl < 32; dl += 2) {
        __syncthreads();
        if (tid < 128) {
            int bb = tid & 63, dp = tid >> 6;
            float xv = st[bb * 33 + dl + dp];
            float f[9];
            f[0] = siluf(xv);
            bspl8(xv, f + 1);
            float2* fr = &fb2[(dp * 64 + bb) * 10];
#pragma unroll
            for (int k = 0; k < 9; k++) fr[k] = make_float2(f[k], f[k]);
            fr[9] = make_float2(xv, xv);           // raw value for skip path
        }
        for (int idx = tid; idx < 2560; idx += 256) {
            int c = idx & 127, row = idx >> 7;  // row = dp*10 + k
            int dp = row / 10, k = row - dp * 10;
            int in = in0 + dl + dp;
            float w;
            if (k == 0) w = g1b[in * UDIM + c];
            else if (k < 9) w = g1s[(in * NB + (k - 1)) * UDIM + c];
            else w = skw[in * UDIM + c];
            wb[row * 128 + c] = w;
        }
        __syncthreads();

#pragma unroll
        for (int dp = 0; dp < 2; dp++) {
#pragma unroll
            for (int k = 0; k < 9; k++) {
                const float* wr = &wb[(dp * 10 + k) * 128 + c0];
                ulonglong2 wa = *(const ulonglong2*)wr;
                ulonglong2 wc = *(const ulonglong2*)(wr + 4);
#pragma unroll
                for (int i = 0; i < 4; i++) {
                    unsigned long long fp =
                        *(const unsigned long long*)&fb2[(dp * 64 + r0 + i) * 10 + k];
                    ffma2(ah2[i][0], fp, wa.x); ffma2(ah2[i][1], fp, wa.y);
                    ffma2(ah2[i][2], fp, wc.x); ffma2(ah2[i][3], fp, wc.y);
                }
            }
            {   // skip path (k = 9, raw value)
                const float* wr = &wb[(dp * 10 + 9) * 128 + c0];
                ulonglong2 wa = *(const ulonglong2*)wr;
                ulonglong2 wc = *(const ulonglong2*)(wr + 4);
#pragma unroll
                for (int i = 0; i < 4; i++) {
                    unsigned long long fp =
                        *(const unsigned long long*)&fb2[(dp * 64 + r0 + i) * 10 + 9];
                    ffma2(as2[i][0], fp, wa.x); ffma2(as2[i][1], fp, wa.y);
                    ffma2(as2[i][2], fp, wc.x); ffma2(as2[i][3], fp, wc.y);
                }
            }
        }
    }

#pragma unroll
    for (int i = 0; i < 4; i++)
#pragma unroll
        for (int j = 0; j < 4; j++) {
            float2 h = *(float2*)&ah2[i][j];
            float2 s = *(float2*)&as2[i][j];
            atomicAdd(&g_hacc[(r0 + i) * UDIM + c0 + 2 * j],     h.x);
            atomicAdd(&g_hacc[(r0 + i) * UDIM + c0 + 2 * j + 1], h.y);
            atomicAdd(&g_skip[(r0 + i) * UDIM + c0 + 2 * j],     s.x);
            atomicAdd(&g_skip[(r0 + i) * UDIM + c0 + 2 * j + 1], s.y);
        }
}

// ---------------- K3: GRKAN layer 2, gate, layernorm, softmax ----------------
__global__ __launch_bounds__(128) void k_grkan2(const float* __restrict__ g2b,
                                                const float* __restrict__ g2s,
                                                const float* __restrict__ gws,
                                                const float* __restrict__ gbs,
                                                const float* __restrict__ gwv,
                                                const float* __restrict__ gbv,
                                                const float* __restrict__ skb,
                                                const float* __restrict__ lng,
                                                const float* __restrict__ lnb) {
    __shared__ float f2[128 * 9];
    __shared__ float h2s[128];
    __shared__ float red[4];

    const int b = blockIdx.x, u = threadIdx.x;

    auto blocksum = [&](float v) -> float {
#pragma unroll
        for (int o = 16; o; o >>= 1) v += __shfl_xor_sync(0xffffffffu, v, o);
        __syncthreads();
        if ((threadIdx.x & 31) == 0) red[threadIdx.x >> 5] = v;
        __syncthreads();
        return red[0] + red[1] + red[2] + red[3];
    };
    auto blockmax = [&](float v) -> float {
#pragma unroll
        for (int o = 16; o; o >>= 1) v = fmaxf(v, __shfl_xor_sync(0xffffffffu, v, o));
        __syncthreads();
        if ((threadIdx.x & 31) == 0) red[threadIdx.x >> 5] = v;
        __syncthreads();
        return fmaxf(fmaxf(red[0], red[1]), fmaxf(red[2], red[3]));
    };

    float hv = g_hacc[b * UDIM + u];
    float sk = g_skip[b * UDIM + u] + skb[u];

    f2[u * 9] = siluf(hv);
    bspl8(hv, &f2[u * 9 + 1]);
    __syncthreads();

    float a0 = 0.f, a1 = 0.f, a2 = 0.f;
    for (int v = 0; v < 128; v++) {
        const float* fr = &f2[v * 9];
        a0 += fr[0] * g2b[v * UDIM + u];
#pragma unroll
        for (int k = 0; k < 4; k++) a1 += fr[1 + k] * g2s[(v * NB + k) * UDIM + u];
#pragma unroll
        for (int k = 4; k < 8; k++) a2 += fr[1 + k] * g2s[(v * NB + k) * UDIM + u];
    }
    float h2 = a0 + a1 + a2;
    h2s[u] = h2;
    __syncthreads();

    float gs = gbs[u], gv = gbv[u];
    for (int v = 0; v < 128; v++) {
        float hh = h2s[v];
        gs += hh * gws[v * UDIM + u];
        gv += hh * gwv[v * UDIM + u];
    }
    float pre = sk + sigm(gs) * gv;

    float s1 = blocksum(pre);
    float s2 = blocksum(pre * pre);
    float mu = s1 * (1.f / 128.f);
    float var = s2 * (1.f / 128.f) - mu * mu;
    float y = lng[u] * (pre - mu) * rsqrtf(var + 1e-3f) + lnb[u];

    float m = blockmax(y);
    float e = __expf(y - m);
    float se = blocksum(e);
    g_wts[b * UDIM + u] = e / se;
}

// ---------------- K4: main KAN (FFMA2), fused weight multiply ----------------
__global__ __launch_bounds__(256, 2) void k_main(const float* __restrict__ x,
                                                 const float* __restrict__ tw,
                                                 const float* __restrict__ kb,
                                                 const float* __restrict__ ksp,
                                                 float* __restrict__ out) {
    __shared__ __align__(16) float xt[128 * 33];     // w = tw*x, 128 rows x 32-dim chunk
    __shared__ __align__(16) float2 fb2[2 * 128 * 9];// duplicated feats [dp][row][9]
    __shared__ __align__(16) float wb[2 * 9 * 128];  // weights [dp][k][u]

    const int tid = threadIdx.x;
    const int row0 = blockIdx.x * 128;
    const int b = row0 >> 10;
    const int s0 = row0 & (SEQ - 1);

    unsigned long long acc2[8][4];
#pragma unroll
    for (int i = 0; i < 8; i++)
#pragma unroll
        for (int j = 0; j < 4; j++) acc2[i][j] = 0ull;

    const int cg = tid & 15, rg = tid >> 4;
    const int c0 = cg * 8, r0 = rg * 8;
    const int frow = tid & 127, fdp = tid >> 7;

    for (int dc = 0; dc < 2; dc++) {
        __syncthreads();  // xt consumers from previous chunk done
        for (int idx = tid; idx < 128 * 32; idx += 256) {
            int r = idx >> 5, dd = idx & 31;
            xt[r * 33 + dd] = tw[s0 + r] * x[(size_t)(row0 + r) * DIM + dc * 32 + dd];
        }

        for (int dl = 0; dl < 32; dl += 2) {
            __syncthreads();  // xt ready (first dl) / fb2,wb consumption done (later)
            {   // features for dims (dl+0, dl+1): all 256 threads
                float xv = xt[frow * 33 + dl + fdp];
                float f[9];
                f[0] = siluf(xv);
                bspl8(xv, f + 1);
                float2* fr = &fb2[(fdp * 128 + frow) * 9];
#pragma unroll
                for (int k = 0; k < 9; k++) fr[k] = make_float2(f[k], f[k]);
            }
            // weights: 18 rows (dp*9+k) x 128 = 576 float4
            for (int idx = tid; idx < 576; idx += 256) {
                int row = idx >> 5, cq = (idx & 31) * 4;
                int dp = row / 9, k = row - dp * 9;
                int dg = dc * 32 + dl + dp;
                float4 w = (k == 0)
                    ? *(const float4*)&kb[dg * UDIM + cq]
                    : *(const float4*)&ksp[(dg * NB + k - 1) * UDIM + cq];
                *(float4*)&wb[row * 128 + cq] = w;
            }
            __syncthreads();

#pragma unroll
            for (int dp = 0; dp < 2; dp++) {
#pragma unroll
                for (int k = 0; k < 9; k++) {
                    const float* wr = &wb[(dp * 9 + k) * 128 + c0];
                    ulonglong2 wa = *(const ulonglong2*)wr;
                    ulonglong2 wc = *(const ulonglong2*)(wr + 4);
#pragma unroll
                    for (int i = 0; i < 8; i++) {
                        unsigned long long fp =
                            *(const unsigned long long*)&fb2[(dp * 128 + r0 + i) * 9 + k];
                        ffma2(acc2[i][0], fp, wa.x); ffma2(acc2[i][1], fp, wa.y);
                        ffma2(acc2[i][2], fp, wc.x); ffma2(acc2[i][3], fp, wc.y);
                    }
                }
            }
        }
    }

    float wv[8];
#pragma unroll
    for (int j = 0; j < 8; j++) wv[j] = g_wts[b * UDIM + c0 + j];
#pragma unroll
    for (int i = 0; i < 8; i++) {
        int row = row0 + r0 + i;
        float2 a0 = *(float2*)&acc2[i][0];
        float2 a1 = *(float2*)&acc2[i][1];
        float2 a2 = *(float2*)&acc2[i][2];
        float2 a3 = *(float2*)&acc2[i][3];
        float4 o0 = make_float4(a0.x * wv[0], a0.y * wv[1], a1.x * wv[2], a1.y * wv[3]);
        float4 o1 = make_float4(a2.x * wv[4], a2.y * wv[5], a3.x * wv[6], a3.y * wv[7]);
        *(float4*)&out[(size_t)row * UDIM + c0] = o0;
        *(float4*)&out[(size_t)row * UDIM + c0 + 4] = o1;
    }
}

// ---------------- launch ----------------
extern "C" void kernel_launch(void* const* d_in, const int* in_sizes, int n_in,
                              void* d_out, int out_size) {
    const float* x   = (const float*)d_in[0];
    const float* tw  = (const float*)d_in[1];
    const float* kb  = (const float*)d_in[2];
    const float* ksp = (const float*)d_in[3];
    const float* g1b = (const float*)d_in[4];
    const float* g1s = (const float*)d_in[5];
    const float* g2b = (const float*)d_in[6];
    const float* g2s = (const float*)d_in[7];
    const float* skw = (const float*)d_in[8];
    const float* skb = (const float*)d_in[9];
    const float* gws = (const float*)d_in[10];
    const float* gbs = (const float*)d_in[11];
    const float* gwv = (const float*)d_in[12];
    const float* gbv = (const float*)d_in[13];
    const float* lng = (const float*)d_in[14];
    const float* lnb = (const float*)d_in[15];
    float* out = (float*)d_out;

    k_sig<<<NBATCH, 256>>>(x, tw);                 // signature + zero accumulators
    k_grkan1<<<130, 256>>>(g1b, g1s, skw);         // split-K layer-1 + skip (FFMA2)
    k_grkan2<<<NBATCH, 128>>>(g2b, g2s, gws, gbs, gwv, gbv, skb, lng, lnb);
    k_main<<<512, 256>>>(x, tw, kb, ksp, out);     // dominant KAN GEMM (FFMA2)
}